// round 8
// baseline (speedup 1.0000x reference)
#include <cuda_runtime.h>
#include <cuda_bf16.h>
#include <math.h>

// Problem constants (fixed shapes from the reference)
#define BATCH 4
#define SEQ   2048
#define DM    1024
#define HEADS 16
#define DK    64
#define BS    (BATCH * SEQ)   // 8192 rows

typedef unsigned long long u64;
union F2U { u64 u; float2 f; };

// packed fp32x2 fma: d = a*b + d (per-lane IEEE fma, sm_100+)
__device__ __forceinline__ void ffma2(u64 &d, u64 a, u64 b) {
    asm("fma.rn.f32x2 %0, %1, %2, %0;" : "+l"(d) : "l"(a), "l"(b));
}
__device__ __forceinline__ void fmul2(u64 &d, u64 c) {
    asm("mul.rn.f32x2 %0, %0, %1;" : "+l"(d) : "l"(c));
}
__device__ __forceinline__ u64 pk2(float x, float y) {
    F2U t; t.f.x = x; t.f.y = y; return t.u;
}

// ---------------- scratch (allocation-free: __device__ globals) ----------------
__device__ float g_qproj[BS * DM];     // [B,S,H*DK]  32 MB
__device__ float g_kh[BS * DK];        // [B,S,DK]     2 MB
__device__ float g_vh[BS * DK];        // [B,S,DK]     2 MB
__device__ float g_attn[BS * DM];      // [B,S,H*DK]  32 MB

// ---------------- f32x2 tiled SGEMM with bias: C = A[M,K] @ W[K,N] + bias -----
// 256 threads. Thread microtile TM x TN, accumulators packed as row-pairs.
// As: K-transposed (pairs along M natural). Bs2: duplicated float2 (x,x).
template <int BM, int BN, int BK, int TM, int TN>
__global__ __launch_bounds__(256, 2) void sgemm_bias_f2_kernel(
    const float* __restrict__ A, const float* __restrict__ W,
    const float* __restrict__ bias, float* __restrict__ C,
    int M, int N, int K)
{
    __shared__ float  As[BK * BM];        // [k][m]
    __shared__ float2 Bs2[BK * BN];       // [k][n] duplicated

    const int tid = threadIdx.x;
    const int tx  = tid % (BN / TN);
    const int ty  = tid / (BN / TN);
    const int rowBase = blockIdx.y * BM;
    const int colBase = blockIdx.x * BN;

    u64 acc2[TM / 2][TN];
#pragma unroll
    for (int i = 0; i < TM / 2; i++)
#pragma unroll
        for (int j = 0; j < TN; j++) acc2[i][j] = 0ull;

    constexpr int A_LD = (BM * BK) / (256 * 4);
    constexpr int B_LD = (BN * BK) / (256 * 4);

    for (int kb = 0; kb < K; kb += BK) {
#pragma unroll
        for (int i = 0; i < A_LD; i++) {
            int l  = tid + i * 256;
            int r  = l / (BK / 4);
            int kq = l % (BK / 4);
            float4 v = *(const float4*)&A[(size_t)(rowBase + r) * K + kb + kq * 4];
            As[(kq * 4 + 0) * BM + r] = v.x;
            As[(kq * 4 + 1) * BM + r] = v.y;
            As[(kq * 4 + 2) * BM + r] = v.z;
            As[(kq * 4 + 3) * BM + r] = v.w;
        }
#pragma unroll
        for (int i = 0; i < B_LD; i++) {
            int l  = tid + i * 256;
            int r  = l / (BN / 4);
            int cq = l % (BN / 4);
            float4 v = *(const float4*)&W[(size_t)(kb + r) * N + colBase + cq * 4];
            float4 d0 = make_float4(v.x, v.x, v.y, v.y);
            float4 d1 = make_float4(v.z, v.z, v.w, v.w);
            *(float4*)&Bs2[r * BN + cq * 4 + 0] = d0;
            *(float4*)&Bs2[r * BN + cq * 4 + 2] = d1;
        }
        __syncthreads();

#pragma unroll 8
        for (int kk = 0; kk < BK; kk++) {
            u64 ap[TM / 2];
            u64 bd[TN];
#pragma unroll
            for (int t = 0; t < TM / 4; t++) {
                ulonglong2 v = *(const ulonglong2*)&As[kk * BM + ty * TM + t * 4];
                ap[t * 2 + 0] = v.x;
                ap[t * 2 + 1] = v.y;
            }
#pragma unroll
            for (int t = 0; t < TN / 2; t++) {
                ulonglong2 v = *(const ulonglong2*)&Bs2[kk * BN + tx * TN + t * 2];
                bd[t * 2 + 0] = v.x;
                bd[t * 2 + 1] = v.y;
            }
#pragma unroll
            for (int i = 0; i < TM / 2; i++)
#pragma unroll
                for (int j = 0; j < TN; j++)
                    ffma2(acc2[i][j], ap[i], bd[j]);
        }
        __syncthreads();
    }

    // epilogue: unpack row pairs, bias, store
#pragma unroll
    for (int ip = 0; ip < TM / 2; ip++) {
        int r0 = rowBase + ty * TM + ip * 2;
        float v0[TN], v1[TN];
#pragma unroll
        for (int j = 0; j < TN; j++) {
            F2U t; t.u = acc2[ip][j];
            float bb = bias[colBase + tx * TN + j];
            v0[j] = t.f.x + bb;
            v1[j] = t.f.y + bb;
        }
#pragma unroll
        for (int j = 0; j < TN; j += 4) {
            *(float4*)&C[(size_t)r0 * N + colBase + tx * TN + j] =
                make_float4(v0[j], v0[j + 1], v0[j + 2], v0[j + 3]);
            *(float4*)&C[(size_t)(r0 + 1) * N + colBase + tx * TN + j] =
                make_float4(v1[j], v1[j + 1], v1[j + 2], v1[j + 3]);
        }
    }
}

// ---------------- tiled MQA flash attention (fp32, f32x2, two-GEMM) ----------
// Block: 64 query rows x one (b, h). 256 threads as 16x16, 4x4 microtiles.
// KV tile = 64 keys. Q^T, K^T(dup), V(dup) in smem; P shares K's buffer.
#define ABR 64
#define ABC 64
#define KR_STRIDE 66   // float2 units, padded (2-way instead of 16-way on store)
#define P_STRIDE  68   // float units, padded

// dynamic smem layout (bytes):
//   Qst : [64][64] float           @0       16384
//   KR2 : [64][KR_STRIDE] float2   @16384   33792   (aliased by Pst [64][68] float)
//   VR2 : [64][64] float2          @50176   32768
#define ATTN_SMEM (16384 + 64 * KR_STRIDE * 8 + 64 * 64 * 8)

__global__ __launch_bounds__(256, 2) void mqa_attn_tiled_kernel(
    const float* __restrict__ qproj,   // [B,S,H*DK]
    const float* __restrict__ kh,      // [B,S,DK]
    const float* __restrict__ vh,      // [B,S,DK]
    float* __restrict__ attn_out)      // [B,S,H*DK]
{
    extern __shared__ float smem[];
    float*  Qst = smem;                                   // [d][r]
    float2* KR2 = (float2*)(smem + 4096);                 // [d][j] dup
    float*  Pst = smem + 4096;                            // [j][r] (alias)
    float2* VR2 = (float2*)((char*)smem + 16384 + 64 * KR_STRIDE * 8); // [j][d] dup

    const int tid = threadIdx.x;
    const int tx  = tid % 16;
    const int ty  = tid / 16;
    const int qt  = blockIdx.x;
    const int h   = blockIdx.y;
    const int b   = blockIdx.z;
    const int row0 = qt * ABR;
    const float scale = 0.125f;   // 1/sqrt(64)

    // ---- load Q tile transposed + pre-scaled: Qst[d][r] ----
#pragma unroll
    for (int p = 0; p < 4; p++) {
        int l  = tid + p * 256;
        int r  = l / 16;
        int d4 = l % 16;
        float4 v = *(const float4*)&qproj[(size_t)(b * SEQ + row0 + r) * DM + h * DK + d4 * 4];
        Qst[(d4 * 4 + 0) * ABR + r] = v.x * scale;
        Qst[(d4 * 4 + 1) * ABR + r] = v.y * scale;
        Qst[(d4 * 4 + 2) * ABR + r] = v.z * scale;
        Qst[(d4 * 4 + 3) * ABR + r] = v.w * scale;
    }

    float m[4], l_[4];
#pragma unroll
    for (int i = 0; i < 4; i++) { m[i] = -1e30f; l_[i] = 0.f; }
    u64 O2[2][4];
#pragma unroll
    for (int ip = 0; ip < 2; ip++)
#pragma unroll
        for (int j = 0; j < 4; j++) O2[ip][j] = 0ull;

    for (int kt = 0; kt < SEQ; kt += ABC) {
        // ---- load K (transposed, dup) and V (natural, dup) tiles ----
#pragma unroll
        for (int p = 0; p < 4; p++) {
            int l  = tid + p * 256;
            int j  = l / 16;
            int d4 = l % 16;
            size_t g = (size_t)(b * SEQ + kt + j) * DK + d4 * 4;
            float4 kv = *(const float4*)&kh[g];
            KR2[(d4 * 4 + 0) * KR_STRIDE + j] = make_float2(kv.x, kv.x);
            KR2[(d4 * 4 + 1) * KR_STRIDE + j] = make_float2(kv.y, kv.y);
            KR2[(d4 * 4 + 2) * KR_STRIDE + j] = make_float2(kv.z, kv.z);
            KR2[(d4 * 4 + 3) * KR_STRIDE + j] = make_float2(kv.w, kv.w);
            float4 vv = *(const float4*)&vh[g];
            *(float4*)&VR2[j * ABC + d4 * 4 + 0] = make_float4(vv.x, vv.x, vv.y, vv.y);
            *(float4*)&VR2[j * ABC + d4 * 4 + 2] = make_float4(vv.z, vv.z, vv.w, vv.w);
        }
        __syncthreads();

        // ---- GEMM1: S[4x4] = Q(rows ty*4..) . K(cols tx*4..) over d=64 ----
        u64 S2[2][4];
#pragma unroll
        for (int ip = 0; ip < 2; ip++)
#pragma unroll
            for (int j = 0; j < 4; j++) S2[ip][j] = 0ull;

#pragma unroll 16
        for (int d = 0; d < 64; d++) {
            ulonglong2 av = *(const ulonglong2*)&Qst[d * ABR + ty * 4]; // rows (0,1),(2,3)
            ulonglong2 b0 = *(const ulonglong2*)&KR2[d * KR_STRIDE + tx * 4];     // j0,j1 dup
            ulonglong2 b1 = *(const ulonglong2*)&KR2[d * KR_STRIDE + tx * 4 + 2]; // j2,j3 dup
            ffma2(S2[0][0], av.x, b0.x); ffma2(S2[0][1], av.x, b0.y);
            ffma2(S2[0][2], av.x, b1.x); ffma2(S2[0][3], av.x, b1.y);
            ffma2(S2[1][0], av.y, b0.x); ffma2(S2[1][1], av.y, b0.y);
            ffma2(S2[1][2], av.y, b1.x); ffma2(S2[1][3], av.y, b1.y);
        }
        __syncthreads();   // done reading K before P overwrites the buffer

        // ---- online softmax (rows spread over 16 lanes of a half-warp) ----
        float s[4][4];
#pragma unroll
        for (int ip = 0; ip < 2; ip++)
#pragma unroll
            for (int j = 0; j < 4; j++) {
                F2U t; t.u = S2[ip][j];
                s[2 * ip + 0][j] = t.f.x;
                s[2 * ip + 1][j] = t.f.y;
            }

        float corr[4];
#pragma unroll
        for (int i = 0; i < 4; i++) {
            float mt = fmaxf(fmaxf(s[i][0], s[i][1]), fmaxf(s[i][2], s[i][3]));
#pragma unroll
            for (int off = 1; off < 16; off <<= 1)
                mt = fmaxf(mt, __shfl_xor_sync(0xffffffffu, mt, off));
            float nm = fmaxf(m[i], mt);
            corr[i] = __expf(m[i] - nm);
            m[i] = nm;
        }
        float p[4][4];
#pragma unroll
        for (int i = 0; i < 4; i++) {
            float ps = 0.f;
#pragma unroll
            for (int j = 0; j < 4; j++) {
                p[i][j] = __expf(s[i][j] - m[i]);
                ps += p[i][j];
            }
#pragma unroll
            for (int off = 1; off < 16; off <<= 1)
                ps += __shfl_xor_sync(0xffffffffu, ps, off);
            l_[i] = l_[i] * corr[i] + ps;
        }
        // rescale O accumulators
#pragma unroll
        for (int ip = 0; ip < 2; ip++) {
            u64 c2 = pk2(corr[2 * ip], corr[2 * ip + 1]);
#pragma unroll
            for (int j = 0; j < 4; j++) fmul2(O2[ip][j], c2);
        }
        // store P (plain, [j][r]) into K's buffer
#pragma unroll
        for (int jj = 0; jj < 4; jj++) {
            *(float4*)&Pst[(tx * 4 + jj) * P_STRIDE + ty * 4] =
                make_float4(p[0][jj], p[1][jj], p[2][jj], p[3][jj]);
        }
        __syncthreads();

        // ---- GEMM2: O[4 rows][4 dcols] += P . V over j=64 ----
#pragma unroll 16
        for (int j = 0; j < 64; j++) {
            ulonglong2 av = *(const ulonglong2*)&Pst[j * P_STRIDE + ty * 4]; // row pairs
            ulonglong2 b0 = *(const ulonglong2*)&VR2[j * ABC + tx * 4];      // d0,d1 dup
            ulonglong2 b1 = *(const ulonglong2*)&VR2[j * ABC + tx * 4 + 2];  // d2,d3 dup
            ffma2(O2[0][0], av.x, b0.x); ffma2(O2[0][1], av.x, b0.y);
            ffma2(O2[0][2], av.x, b1.x); ffma2(O2[0][3], av.x, b1.y);
            ffma2(O2[1][0], av.y, b0.x); ffma2(O2[1][1], av.y, b0.y);
            ffma2(O2[1][2], av.y, b1.x); ffma2(O2[1][3], av.y, b1.y);
        }
        __syncthreads();   // before next tile's K/V overwrite
    }

    // ---- epilogue: normalize, store ----
#pragma unroll
    for (int ip = 0; ip < 2; ip++) {
        int r0 = row0 + ty * 4 + 2 * ip;
        float inv0 = 1.f / l_[2 * ip + 0];
        float inv1 = 1.f / l_[2 * ip + 1];
        float o0[4], o1[4];
#pragma unroll
        for (int j = 0; j < 4; j++) {
            F2U t; t.u = O2[ip][j];
            o0[j] = t.f.x * inv0;
            o1[j] = t.f.y * inv1;
        }
        *(float4*)&attn_out[(size_t)(b * SEQ + r0) * DM + h * DK + tx * 4] =
            make_float4(o0[0], o0[1], o0[2], o0[3]);
        *(float4*)&attn_out[(size_t)(b * SEQ + r0 + 1) * DM + h * DK + tx * 4] =
            make_float4(o1[0], o1[1], o1[2], o1[3]);
    }
}

// ---------------- launch ------------------------------------------------------
extern "C" void kernel_launch(void* const* d_in, const int* in_sizes, int n_in,
                              void* d_out, int out_size)
{
    const float* q  = (const float*)d_in[0];
    const float* k  = (const float*)d_in[1];
    const float* v  = (const float*)d_in[2];
    const float* Wq = (const float*)d_in[3];
    const float* bq = (const float*)d_in[4];
    const float* Wk = (const float*)d_in[5];
    const float* bk = (const float*)d_in[6];
    const float* Wv = (const float*)d_in[7];
    const float* bv = (const float*)d_in[8];
    const float* Wo = (const float*)d_in[9];
    const float* bo = (const float*)d_in[10];
    float* out = (float*)d_out;

    float* qproj; cudaGetSymbolAddress((void**)&qproj, g_qproj);
    float* kh;    cudaGetSymbolAddress((void**)&kh,    g_kh);
    float* vh;    cudaGetSymbolAddress((void**)&vh,    g_vh);
    float* attn;  cudaGetSymbolAddress((void**)&attn,  g_attn);

    cudaFuncSetAttribute(mqa_attn_tiled_kernel,
                         cudaFuncAttributeMaxDynamicSharedMemorySize, ATTN_SMEM);

    // 1) Q projection: [8192,1024] @ [1024,1024] + bq
    {
        dim3 grid(DM / 128, BS / 128);
        sgemm_bias_f2_kernel<128, 128, 16, 8, 8><<<grid, 256>>>(q, Wq, bq, qproj, BS, DM, DM);
    }
    // 2) K / V projections: [8192,1024] @ [1024,64] + b
    {
        dim3 grid(DK / 64, BS / 128);
        sgemm_bias_f2_kernel<128, 64, 16, 8, 4><<<grid, 256>>>(k, Wk, bk, kh, BS, DK, DM);
        sgemm_bias_f2_kernel<128, 64, 16, 8, 4><<<grid, 256>>>(v, Wv, bv, vh, BS, DK, DM);
    }
    // 3) tiled MQA flash attention
    {
        dim3 grid(SEQ / ABR, HEADS, BATCH);
        mqa_attn_tiled_kernel<<<grid, 256, ATTN_SMEM>>>(qproj, kh, vh, attn);
    }
    // 4) Output projection: [8192,1024] @ [1024,1024] + bo
    {
        dim3 grid(DM / 128, BS / 128);
        sgemm_bias_f2_kernel<128, 128, 16, 8, 8><<<grid, 256>>>(attn, Wo, bo, out, BS, DM, DM);
    }
}

// round 10
// speedup vs baseline: 2.5164x; 2.5164x over previous
#include <cuda_runtime.h>
#include <cuda_bf16.h>
#include <math.h>

// Problem constants (fixed shapes from the reference)
#define BATCH 4
#define SEQ   2048
#define DM    1024
#define HEADS 16
#define DK    64
#define BS    (BATCH * SEQ)   // 8192 rows

typedef unsigned long long u64;
union F2U { u64 u; float2 f; };

// packed fp32x2 fma: d = a*b + d (per-lane IEEE fma, sm_100+)
__device__ __forceinline__ void ffma2(u64 &d, u64 a, u64 b) {
    asm("fma.rn.f32x2 %0, %1, %2, %0;" : "+l"(d) : "l"(a), "l"(b));
}
__device__ __forceinline__ void fmul2(u64 &d, u64 c) {
    asm("mul.rn.f32x2 %0, %0, %1;" : "+l"(d) : "l"(c));
}
__device__ __forceinline__ u64 pk2(float x, float y) {
    F2U t; t.f.x = x; t.f.y = y; return t.u;
}

// ---------------- scratch (allocation-free: __device__ globals) ----------------
__device__ float g_qproj[BS * DM];     // [B,S,H*DK]  32 MB
__device__ float g_kh[BS * DK];        // [B,S,DK]     2 MB
__device__ float g_vh[BS * DK];        // [B,S,DK]     2 MB
__device__ float g_attn[BS * DM];      // [B,S,H*DK]  32 MB

// ---------------- R1 scalar tiled SGEMM with bias (known-good) ----------------
// C[M,N] = A[M,K] @ W[K,N] + bias. BM/TM * BN/TN == 256 threads.
template <int BM, int BN, int BK, int TM, int TN>
__global__ __launch_bounds__(256) void sgemm_bias_kernel(
    const float* __restrict__ A, const float* __restrict__ W,
    const float* __restrict__ bias, float* __restrict__ C,
    int M, int N, int K)
{
    __shared__ float As[BK][BM];   // K-transposed A tile
    __shared__ float Bs[BK][BN];

    const int tid = threadIdx.x;
    const int tx  = tid % (BN / TN);
    const int ty  = tid / (BN / TN);
    const int rowBase = blockIdx.y * BM;
    const int colBase = blockIdx.x * BN;

    float acc[TM][TN];
#pragma unroll
    for (int i = 0; i < TM; i++)
#pragma unroll
        for (int j = 0; j < TN; j++) acc[i][j] = 0.f;

    constexpr int A_LD = (BM * BK) / (256 * 4);
    constexpr int B_LD = (BN * BK) / (256 * 4);

    for (int kb = 0; kb < K; kb += BK) {
#pragma unroll
        for (int i = 0; i < A_LD; i++) {
            int l  = tid + i * 256;
            int r  = l / (BK / 4);
            int kq = l % (BK / 4);
            float4 v = *(const float4*)&A[(size_t)(rowBase + r) * K + kb + kq * 4];
            As[kq * 4 + 0][r] = v.x;
            As[kq * 4 + 1][r] = v.y;
            As[kq * 4 + 2][r] = v.z;
            As[kq * 4 + 3][r] = v.w;
        }
#pragma unroll
        for (int i = 0; i < B_LD; i++) {
            int l  = tid + i * 256;
            int r  = l / (BN / 4);
            int cq = l % (BN / 4);
            *(float4*)&Bs[r][cq * 4] =
                *(const float4*)&W[(size_t)(kb + r) * N + colBase + cq * 4];
        }
        __syncthreads();

#pragma unroll
        for (int kk = 0; kk < BK; kk++) {
            float a[TM], b[TN];
#pragma unroll
            for (int i = 0; i < TM; i += 4) {
                float4 v = *(const float4*)&As[kk][ty * TM + i];
                a[i] = v.x; a[i + 1] = v.y; a[i + 2] = v.z; a[i + 3] = v.w;
            }
#pragma unroll
            for (int j = 0; j < TN; j += 4) {
                float4 v = *(const float4*)&Bs[kk][tx * TN + j];
                b[j] = v.x; b[j + 1] = v.y; b[j + 2] = v.z; b[j + 3] = v.w;
            }
#pragma unroll
            for (int i = 0; i < TM; i++)
#pragma unroll
                for (int j = 0; j < TN; j++)
                    acc[i][j] = fmaf(a[i], b[j], acc[i][j]);
        }
        __syncthreads();
    }

#pragma unroll
    for (int i = 0; i < TM; i++) {
        int row = rowBase + ty * TM + i;
#pragma unroll
        for (int j = 0; j < TN; j += 4) {
            int col = colBase + tx * TN + j;
            float4 o;
            o.x = acc[i][j + 0] + bias[col + 0];
            o.y = acc[i][j + 1] + bias[col + 1];
            o.z = acc[i][j + 2] + bias[col + 2];
            o.w = acc[i][j + 3] + bias[col + 3];
            *(float4*)&C[(size_t)row * N + col] = o;
        }
    }
}

// ---------------- MQA flash attention: R1 structure + d-packed f32x2 ---------
// One thread = one query row. Block = BR rows of one (b,h). K/V tiles in smem,
// rows read via warp-broadcast LDS.128 (all lanes same address, conflict-free).
// f32x2 pairs run along the CONTIGUOUS d dimension -> no operand duplication.
#define BR 128
#define BC 32

__global__ __launch_bounds__(BR) void mqa_attn_kernel(
    const float* __restrict__ qproj,   // [B,S,H*DK]
    const float* __restrict__ kh,      // [B,S,DK]
    const float* __restrict__ vh,      // [B,S,DK]
    float* __restrict__ attn_out)      // [B,S,H*DK]
{
    __shared__ float Ks[BC][DK];
    __shared__ float Vs[BC][DK];

    const int t  = threadIdx.x;
    const int qt = blockIdx.x;
    const int h  = blockIdx.y;
    const int b  = blockIdx.z;
    const int row = qt * BR + t;

    const float scale = 0.125f;    // 1/sqrt(64)

    // this thread's Q row, pre-scaled, packed as 32 d-pairs
    u64 q2[DK / 2];
    {
        const float* qp = qproj + ((size_t)(b * SEQ + row)) * DM + h * DK;
#pragma unroll
        for (int d = 0; d < DK; d += 4) {
            float4 v = *(const float4*)&qp[d];
            q2[d / 2 + 0] = pk2(v.x * scale, v.y * scale);
            q2[d / 2 + 1] = pk2(v.z * scale, v.w * scale);
        }
    }

    u64 O2[DK / 2];                   // O2[i] = (O[2i], O[2i+1])
#pragma unroll
    for (int i = 0; i < DK / 2; i++) O2[i] = 0ull;
    float m = -1e30f;
    float l = 0.f;

    for (int kt = 0; kt < SEQ; kt += BC) {
        // cooperative K/V tile load (coalesced float4)
#pragma unroll
        for (int i = 0; i < (BC * DK) / (BR * 4); i++) {   // 4 iterations
            int l4 = t + i * BR;
            int r  = l4 / (DK / 4);
            int c  = (l4 % (DK / 4)) * 4;
            size_t g = ((size_t)(b * SEQ + kt + r)) * DK + c;
            *(float4*)&Ks[r][c] = *(const float4*)&kh[g];
            *(float4*)&Vs[r][c] = *(const float4*)&vh[g];
        }
        __syncthreads();

        // scores: QK^T via d-packed FFMA2 (K rows broadcast across the warp)
        float s[BC];
#pragma unroll
        for (int j = 0; j < BC; j++) {
            const ulonglong2* kr = (const ulonglong2*)Ks[j];
            u64 acc = 0ull;
#pragma unroll
            for (int d4 = 0; d4 < DK / 4; d4++) {
                ulonglong2 kv = kr[d4];                    // LDS.128 broadcast
                ffma2(acc, q2[d4 * 2 + 0], kv.x);
                ffma2(acc, q2[d4 * 2 + 1], kv.y);
            }
            F2U f; f.u = acc;
            s[j] = f.f.x + f.f.y;                          // fold even/odd sums
        }

        // online softmax update (identical to R1)
        float mt = m;
#pragma unroll
        for (int j = 0; j < BC; j++) mt = fmaxf(mt, s[j]);
        float corr = __expf(m - mt);
        m = mt;
        l *= corr;
        {
            u64 c2 = pk2(corr, corr);
#pragma unroll
            for (int i = 0; i < DK / 2; i++) fmul2(O2[i], c2);
        }

#pragma unroll
        for (int j = 0; j < BC; j++) {
            float p = __expf(s[j] - m);
            l += p;
            u64 p2 = pk2(p, p);                            // one dup per key
            const ulonglong2* vr = (const ulonglong2*)Vs[j];
#pragma unroll
            for (int d4 = 0; d4 < DK / 4; d4++) {
                ulonglong2 vv = vr[d4];                    // LDS.128 broadcast
                ffma2(O2[d4 * 2 + 0], p2, vv.x);
                ffma2(O2[d4 * 2 + 1], p2, vv.y);
            }
        }
        __syncthreads();
    }

    // normalize + store
    float inv = 1.f / l;
    float* op = attn_out + ((size_t)(b * SEQ + row)) * DM + h * DK;
#pragma unroll
    for (int d = 0; d < DK; d += 4) {
        F2U a, bb;
        a.u  = O2[d / 2 + 0];
        bb.u = O2[d / 2 + 1];
        float4 o;
        o.x = a.f.x * inv;
        o.y = a.f.y * inv;
        o.z = bb.f.x * inv;
        o.w = bb.f.y * inv;
        *(float4*)&op[d] = o;
    }
}

// ---------------- launch ------------------------------------------------------
extern "C" void kernel_launch(void* const* d_in, const int* in_sizes, int n_in,
                              void* d_out, int out_size)
{
    const float* q  = (const float*)d_in[0];
    const float* k  = (const float*)d_in[1];
    const float* v  = (const float*)d_in[2];
    const float* Wq = (const float*)d_in[3];
    const float* bq = (const float*)d_in[4];
    const float* Wk = (const float*)d_in[5];
    const float* bk = (const float*)d_in[6];
    const float* Wv = (const float*)d_in[7];
    const float* bv = (const float*)d_in[8];
    const float* Wo = (const float*)d_in[9];
    const float* bo = (const float*)d_in[10];
    float* out = (float*)d_out;

    float* qproj; cudaGetSymbolAddress((void**)&qproj, g_qproj);
    float* kh;    cudaGetSymbolAddress((void**)&kh,    g_kh);
    float* vh;    cudaGetSymbolAddress((void**)&vh,    g_vh);
    float* attn;  cudaGetSymbolAddress((void**)&attn,  g_attn);

    // 1) Q projection: [8192,1024] @ [1024,1024] + bq
    {
        dim3 grid(DM / 128, BS / 128);
        sgemm_bias_kernel<128, 128, 16, 8, 8><<<grid, 256>>>(q, Wq, bq, qproj, BS, DM, DM);
    }
    // 2) K / V projections: [8192,1024] @ [1024,64] + b
    {
        dim3 grid(DK / 64, BS / 128);
        sgemm_bias_kernel<128, 64, 16, 8, 4><<<grid, 256>>>(k, Wk, bk, kh, BS, DK, DM);
        sgemm_bias_kernel<128, 64, 16, 8, 4><<<grid, 256>>>(v, Wv, bv, vh, BS, DK, DM);
    }
    // 3) MQA flash attention (d-packed f32x2)
    {
        dim3 grid(SEQ / BR, HEADS, BATCH);
        mqa_attn_kernel<<<grid, BR>>>(qproj, kh, vh, attn);
    }
    // 4) Output projection: [8192,1024] @ [1024,1024] + bo
    {
        dim3 grid(DM / 128, BS / 128);
        sgemm_bias_kernel<128, 128, 16, 8, 8><<<grid, 256>>>(attn, Wo, bo, out, BS, DM, DM);
    }
}